// round 7
// baseline (speedup 1.0000x reference)
#include <cuda_runtime.h>
#include <cuda_bf16.h>

// HarmonicLowering: out[b, k*32+c, f, t] = w * x[b,c,idx,t] + (1-w) * x[b,c,idx1,t]
//   k in 1..4, idx = (f*k)>>2, w = 1 - (f*k & 3)*0.25, idx1 = min(idx+1, 255)
// x = (8, 32, 256, 512) f32 (128 MiB); out = (8, 128, 256, 512) f32 (512 MiB).
// Pure HBM-bound: t-dim handled as float4 -> 16B coalesced; 2 outputs/thread (MLP=4).

static constexpr int B = 8;
static constexpr int C = 32;
static constexpr int F = 256;
static constexpr int T4 = 128;            // 512 floats / 4
static constexpr long long OUT_V4 = (long long)B * 4 * C * F * T4;  // 33,554,432
static constexpr int VPT = 2;             // v4 elements per thread

__global__ void __launch_bounds__(256) harmonic_lowering_kernel(
    const float4* __restrict__ x, float4* __restrict__ out)
{
    unsigned int i0 = (blockIdx.x * blockDim.x + threadIdx.x) * VPT;

#pragma unroll
    for (int v = 0; v < VPT; ++v) {
        unsigned int i = i0 + v;

        // output v4 index decomposition: (((b*128 + kc)*256 + f)*128 + t4)
        unsigned int t4 = i & 127u;
        unsigned int f  = (i >> 7) & 255u;
        unsigned int kc = (i >> 15) & 127u;
        unsigned int b  = i >> 22;

        unsigned int k  = (kc >> 5) + 1u;     // 1..4
        unsigned int ch = kc & 31u;

        unsigned int prod = f * k;
        unsigned int idx  = prod >> 2;
        float w = 1.0f - (float)(prod & 3u) * 0.25f;
        unsigned int idx1 = min(idx + 1u, (unsigned int)(F - 1));

        unsigned int base = (b * C + ch) * F;             // row index into x
        const float4 g0 = x[((base + idx ) << 7) + t4];
        const float4 g1 = x[((base + idx1) << 7) + t4];

        float wm = 1.0f - w;
        float4 o;
        o.x = fmaf(w, g0.x, wm * g1.x);
        o.y = fmaf(w, g0.y, wm * g1.y);
        o.z = fmaf(w, g0.z, wm * g1.z);
        o.w = fmaf(w, g0.w, wm * g1.w);
        out[i] = o;
    }
}

extern "C" void kernel_launch(void* const* d_in, const int* in_sizes, int n_in,
                              void* d_out, int out_size)
{
    const float4* x = (const float4*)d_in[0];
    float4* out = (float4*)d_out;
    const int threads = 256;
    const int blocks = (int)(OUT_V4 / (threads * VPT));   // 65536
    harmonic_lowering_kernel<<<blocks, threads>>>(x, out);
}

// round 14
// speedup vs baseline: 1.0925x; 1.0925x over previous
#include <cuda_runtime.h>
#include <cuda_bf16.h>

// HarmonicLowering: out[b, k*32+c, f, t] = w * x[b,c,idx,t] + (1-w) * x[b,c,idx1,t]
//   k in 1..4, idx = (f*k)>>2, w = 1 - (f*k & 3)*0.25, idx1 = min(idx+1, 255)
// x = (8, 32, 256, 512) f32 (128 MiB); out = (8, 128, 256, 512) f32 (512 MiB).
//
// R7 ncu: L1tex was the limiter (82%) because VPT=2 thread-consecutive indices
// gave lane-stride-2 (32B) access -> 2x sectors per LDG/STG. Fix: each thread
// handles i and i + OUT_V4/2 (grid-split), so every memory instruction is
// lane-stride-1, fully coalesced. MLP=4 loads per thread retained.

static constexpr int B = 8;
static constexpr int C = 32;
static constexpr int F = 256;
static constexpr int T4 = 128;            // 512 floats / 4
static constexpr unsigned int OUT_V4 = (unsigned int)B * 4 * C * F * T4;  // 33,554,432
static constexpr unsigned int HALF_V4 = OUT_V4 / 2;                       // 16,777,216

__global__ void __launch_bounds__(256) harmonic_lowering_kernel(
    const float4* __restrict__ x, float4* __restrict__ out)
{
    unsigned int i0 = blockIdx.x * blockDim.x + threadIdx.x;   // < 2^24

#pragma unroll
    for (int v = 0; v < 2; ++v) {
        unsigned int i = i0 + (unsigned int)v * HALF_V4;       // coalesced halves

        // output v4 index decomposition: (((b*128 + kc)*256 + f)*128 + t4)
        unsigned int t4 = i & 127u;
        unsigned int f  = (i >> 7) & 255u;
        unsigned int kc = (i >> 15) & 127u;
        unsigned int b  = i >> 22;

        unsigned int k  = (kc >> 5) + 1u;     // 1..4
        unsigned int ch = kc & 31u;

        unsigned int prod = f * k;
        unsigned int idx  = prod >> 2;
        float w = 1.0f - (float)(prod & 3u) * 0.25f;
        unsigned int idx1 = min(idx + 1u, (unsigned int)(F - 1));

        unsigned int base = (b * C + ch) * F;             // row index into x
        const float4 g0 = x[((base + idx ) << 7) + t4];
        const float4 g1 = x[((base + idx1) << 7) + t4];

        float wm = 1.0f - w;
        float4 o;
        o.x = fmaf(w, g0.x, wm * g1.x);
        o.y = fmaf(w, g0.y, wm * g1.y);
        o.z = fmaf(w, g0.z, wm * g1.z);
        o.w = fmaf(w, g0.w, wm * g1.w);
        out[i] = o;
    }
}

extern "C" void kernel_launch(void* const* d_in, const int* in_sizes, int n_in,
                              void* d_out, int out_size)
{
    const float4* x = (const float4*)d_in[0];
    float4* out = (float4*)d_out;
    const int threads = 256;
    const int blocks = (int)(HALF_V4 / threads);          // 65536
    harmonic_lowering_kernel<<<blocks, threads>>>(x, out);
}